// round 10
// baseline (speedup 1.0000x reference)
#include <cuda_runtime.h>
#include <cstdint>

// Problem constants (fixed by the dataset)
#define NMAX      50000
#define IN_FEATS  256
#define NHEADS    4
#define OUTF      64
#define HF        (NHEADS * OUTF)   // 256 = per-node projected width
#define NEG_SLOPE 0.2f
#define MAXDEG    16                // dataset uses fixed deg=16

// ---------------------------------------------------------------------------
// Scratch (no cudaMalloc allowed)
// ---------------------------------------------------------------------------
__device__ float g_h[(size_t)NMAX * HF];        // 51.2 MB projected features
__device__ float g_attn_row[(size_t)NMAX * NHEADS];
__device__ float g_attn_col[(size_t)NMAX * NHEADS];

// ---------------------------------------------------------------------------
// Kernel 1: tf32 tensor-core GEMM  h[M,256] = feat[M,256] @ W[256,256]
// CTA tile 128x128x16, 8 warps in 2(M)x4(N), warp tile 64x32,
// mma.sync.aligned.m16n8k8 tf32, fp32 accumulate. Double-buffered smem.
//
// Fragment-paired smem layouts (all fragment fetches are LDS.64):
//  A: per (mb 0..7, kc 0..1) block of 16 rows x 8 k (128 words):
//     addr = blk*128 + kk*16 + (rr&7)*2 + (rr>>3)
//     -> pair (row gid, row gid+8) at fixed k is contiguous.
//  B: per (kc 0..1, nb 0..15) block of 8 k x 8 cols (64 words), XOR-swizzled:
//     addr = blk*64 + (cc ^ (nb&7))*8 + (kkl&3)*2 + (kkl>>2)
//     -> pair (k tig, k tig+4) at fixed col is contiguous.
//
// Fused epilogue: per-row attn_l/attn_r dot products; even warp_n stages
// partials in smem, odd warp_n combines + plain STG (no atomics, no zeroing).
// ---------------------------------------------------------------------------
#define GBM 128
#define GBN 128
#define GBK 16

__device__ __forceinline__ uint32_t f2tf32(float x) {
    uint32_t r;
    asm("cvt.rna.tf32.f32 %0, %1;" : "=r"(r) : "f"(x));
    return r;
}

__device__ __forceinline__ void mma_tf32(float* c, const uint32_t* a,
                                         const uint32_t* b) {
    asm volatile(
        "mma.sync.aligned.m16n8k8.row.col.f32.tf32.tf32.f32 "
        "{%0,%1,%2,%3}, {%4,%5,%6,%7}, {%8,%9}, {%0,%1,%2,%3};"
        : "+f"(c[0]), "+f"(c[1]), "+f"(c[2]), "+f"(c[3])
        : "r"(a[0]), "r"(a[1]), "r"(a[2]), "r"(a[3]), "r"(b[0]), "r"(b[1]));
}

__global__ __launch_bounds__(256, 2) void gemm_tf32_kernel(
    const float* __restrict__ A,        // [M, 256]
    const float* __restrict__ B,        // [256, 256]
    const float* __restrict__ attn_l,   // [256]
    const float* __restrict__ attn_r,   // [256]
    int M)
{
    const int K = IN_FEATS;
    const int N = HF;

    __shared__ uint32_t As[2][2048];    // 2 x 8 KB
    __shared__ uint32_t Bs[2][2048];    // 2 x 8 KB
    __shared__ float    sred[GBM][4];   // 2 KB: [row][head_local*2 + {l,r}]

    const int tid  = threadIdx.x;
    const int lane = tid & 31;
    const int warp = tid >> 5;
    const int warp_m = warp >> 2;      // 0..1 -> 64-row strip
    const int warp_n = warp & 3;       // 0..3 -> 32-col strip

    const int block_m = blockIdx.x * GBM;
    const int block_n = blockIdx.y * GBN;

    // --- global->smem loader maps ---
    // A: thread covers row a_row, one k-chunk of 8
    const int a_row = tid >> 1;                       // 0..127
    const int a_kc  = tid & 1;                        // 0..1
    const int a_base = ((a_row >> 4) * 2 + a_kc) * 128
                     + (a_row & 7) * 2 + ((a_row >> 3) & 1);
    // B: thread covers k-row b_kk, one 8-col block b_nb
    const int b_kk  = tid >> 4;                       // 0..15
    const int b_nb  = tid & 15;                       // 0..15
    const int b_sw  = b_nb & 7;
    const int b_base = ((b_kk >> 3) * 16 + b_nb) * 64
                     + (b_kk & 3) * 2 + ((b_kk >> 2) & 1);

    const int gid = lane >> 2;                  // 0..7
    const int tig = lane & 3;                   // 0..3

    float acc[4][4][4];
#pragma unroll
    for (int mt = 0; mt < 4; mt++)
#pragma unroll
        for (int nt = 0; nt < 4; nt++)
#pragma unroll
            for (int i = 0; i < 4; i++) acc[mt][nt][i] = 0.0f;

    const int gm = block_m + a_row;
    float4 pa0, pa1, pb0, pb1;

    // ---- load tile 0 into registers, then smem ----
    {
        if (gm < M) {
            const float* ap = A + (size_t)gm * K + a_kc * 8;
            pa0 = *reinterpret_cast<const float4*>(ap);
            pa1 = *reinterpret_cast<const float4*>(ap + 4);
        } else {
            pa0 = make_float4(0.f, 0.f, 0.f, 0.f); pa1 = pa0;
        }
        const float* bp = B + (size_t)b_kk * N + block_n + b_nb * 8;
        pb0 = *reinterpret_cast<const float4*>(bp);
        pb1 = *reinterpret_cast<const float4*>(bp + 4);
    }
    {
        uint32_t* as = &As[0][a_base];
        as[0]  = f2tf32(pa0.x); as[16] = f2tf32(pa0.y);
        as[32] = f2tf32(pa0.z); as[48] = f2tf32(pa0.w);
        as[64] = f2tf32(pa1.x); as[80] = f2tf32(pa1.y);
        as[96] = f2tf32(pa1.z); as[112] = f2tf32(pa1.w);
        uint32_t* bs = &Bs[0][b_base];
        bs[(0 ^ b_sw) << 3] = f2tf32(pb0.x);
        bs[(1 ^ b_sw) << 3] = f2tf32(pb0.y);
        bs[(2 ^ b_sw) << 3] = f2tf32(pb0.z);
        bs[(3 ^ b_sw) << 3] = f2tf32(pb0.w);
        bs[(4 ^ b_sw) << 3] = f2tf32(pb1.x);
        bs[(5 ^ b_sw) << 3] = f2tf32(pb1.y);
        bs[(6 ^ b_sw) << 3] = f2tf32(pb1.z);
        bs[(7 ^ b_sw) << 3] = f2tf32(pb1.w);
    }
    __syncthreads();

    const int NT = K / GBK;   // 16 iterations
    for (int t = 0; t < NT; t++) {
        const int cur = t & 1;

        // prefetch next tile from global
        if (t < NT - 1) {
            const int k0 = (t + 1) * GBK;
            if (gm < M) {
                const float* ap = A + (size_t)gm * K + k0 + a_kc * 8;
                pa0 = *reinterpret_cast<const float4*>(ap);
                pa1 = *reinterpret_cast<const float4*>(ap + 4);
            } else {
                pa0 = make_float4(0.f, 0.f, 0.f, 0.f); pa1 = pa0;
            }
            const float* bp = B + (size_t)(k0 + b_kk) * N + block_n + b_nb * 8;
            pb0 = *reinterpret_cast<const float4*>(bp);
            pb1 = *reinterpret_cast<const float4*>(bp + 4);
        }

        // compute: 2 k-chunks of 8
#pragma unroll
        for (int kc = 0; kc < 2; kc++) {
            uint32_t af[4][4], bf[4][2];
#pragma unroll
            for (int mt = 0; mt < 4; mt++) {
                const int baseA = (((warp_m * 4 + mt) * 2 + kc) << 7)
                                + gid * 2;
                const uint2 a01 = *reinterpret_cast<const uint2*>(
                    &As[cur][baseA + tig * 16]);
                const uint2 a23 = *reinterpret_cast<const uint2*>(
                    &As[cur][baseA + (tig + 4) * 16]);
                af[mt][0] = a01.x; af[mt][1] = a01.y;
                af[mt][2] = a23.x; af[mt][3] = a23.y;
            }
#pragma unroll
            for (int nt = 0; nt < 4; nt++) {
                const int nb = warp_n * 4 + nt;
                const uint2 b01 = *reinterpret_cast<const uint2*>(
                    &Bs[cur][((kc * 16 + nb) << 6)
                             + ((gid ^ (nb & 7)) << 3) + tig * 2]);
                bf[nt][0] = b01.x; bf[nt][1] = b01.y;
            }
#pragma unroll
            for (int mt = 0; mt < 4; mt++)
#pragma unroll
                for (int nt = 0; nt < 4; nt++)
                    mma_tf32(acc[mt][nt], af[mt], bf[nt]);
        }

        // store prefetched tile to other buffer
        if (t < NT - 1) {
            const int nxt = (t + 1) & 1;
            uint32_t* as = &As[nxt][a_base];
            as[0]  = f2tf32(pa0.x); as[16] = f2tf32(pa0.y);
            as[32] = f2tf32(pa0.z); as[48] = f2tf32(pa0.w);
            as[64] = f2tf32(pa1.x); as[80] = f2tf32(pa1.y);
            as[96] = f2tf32(pa1.z); as[112] = f2tf32(pa1.w);
            uint32_t* bs = &Bs[nxt][b_base];
            bs[(0 ^ b_sw) << 3] = f2tf32(pb0.x);
            bs[(1 ^ b_sw) << 3] = f2tf32(pb0.y);
            bs[(2 ^ b_sw) << 3] = f2tf32(pb0.z);
            bs[(3 ^ b_sw) << 3] = f2tf32(pb0.w);
            bs[(4 ^ b_sw) << 3] = f2tf32(pb1.x);
            bs[(5 ^ b_sw) << 3] = f2tf32(pb1.y);
            bs[(6 ^ b_sw) << 3] = f2tf32(pb1.z);
            bs[(7 ^ b_sw) << 3] = f2tf32(pb1.w);
            __syncthreads();
        }
    }

    // ---- epilogue 1: write h ----
#pragma unroll
    for (int mt = 0; mt < 4; mt++) {
        const int r0 = block_m + warp_m * 64 + mt * 16 + gid;
        const int r1 = r0 + 8;
#pragma unroll
        for (int nt = 0; nt < 4; nt++) {
            const int cn = block_n + warp_n * 32 + nt * 8 + tig * 2;
            if (r0 < M) {
                float2 v = make_float2(acc[mt][nt][0], acc[mt][nt][1]);
                *reinterpret_cast<float2*>(g_h + (size_t)r0 * HF + cn) = v;
            }
            if (r1 < M) {
                float2 v = make_float2(acc[mt][nt][2], acc[mt][nt][3]);
                *reinterpret_cast<float2*>(g_h + (size_t)r1 * HF + cn) = v;
            }
        }
    }

    // ---- epilogue 2: fused attn dot products (smem reduce across warp_n
    //      pairs, then plain store; each (row, head) owned by this CTA) ----
    {
        const int hl   = warp_n >> 1;           // head-local: 0..1
        const int head = (block_n >> 6) + hl;   // global head
        float al[8], ar[8];
#pragma unroll
        for (int nt = 0; nt < 4; nt++) {
            const int c = block_n + warp_n * 32 + nt * 8 + tig * 2;
            al[nt * 2]     = attn_l[c];
            al[nt * 2 + 1] = attn_l[c + 1];
            ar[nt * 2]     = attn_r[c];
            ar[nt * 2 + 1] = attn_r[c + 1];
        }

        __syncthreads();   // smem buffers free; sred becomes valid

        // phase 1: even warp_n stages partials
        if ((warp_n & 1) == 0) {
#pragma unroll
            for (int mt = 0; mt < 4; mt++) {
                float pl0 = 0.f, pr0 = 0.f, pl1 = 0.f, pr1 = 0.f;
#pragma unroll
                for (int nt = 0; nt < 4; nt++) {
                    pl0 = fmaf(acc[mt][nt][0], al[nt*2],   pl0);
                    pl0 = fmaf(acc[mt][nt][1], al[nt*2+1], pl0);
                    pr0 = fmaf(acc[mt][nt][0], ar[nt*2],   pr0);
                    pr0 = fmaf(acc[mt][nt][1], ar[nt*2+1], pr0);
                    pl1 = fmaf(acc[mt][nt][2], al[nt*2],   pl1);
                    pl1 = fmaf(acc[mt][nt][3], al[nt*2+1], pl1);
                    pr1 = fmaf(acc[mt][nt][2], ar[nt*2],   pr1);
                    pr1 = fmaf(acc[mt][nt][3], ar[nt*2+1], pr1);
                }
#pragma unroll
                for (int off = 1; off <= 2; off <<= 1) {
                    pl0 += __shfl_xor_sync(0xFFFFFFFFu, pl0, off);
                    pr0 += __shfl_xor_sync(0xFFFFFFFFu, pr0, off);
                    pl1 += __shfl_xor_sync(0xFFFFFFFFu, pl1, off);
                    pr1 += __shfl_xor_sync(0xFFFFFFFFu, pr1, off);
                }
                if (tig == 0) {
                    const int rl0 = warp_m * 64 + mt * 16 + gid;
                    sred[rl0][hl * 2]     = pl0;
                    sred[rl0][hl * 2 + 1] = pr0;
                    sred[rl0 + 8][hl * 2]     = pl1;
                    sred[rl0 + 8][hl * 2 + 1] = pr1;
                }
            }
        }
        __syncthreads();

        // phase 2: odd warp_n combines and stores
        if ((warp_n & 1) == 1) {
#pragma unroll
            for (int mt = 0; mt < 4; mt++) {
                float pl0 = 0.f, pr0 = 0.f, pl1 = 0.f, pr1 = 0.f;
#pragma unroll
                for (int nt = 0; nt < 4; nt++) {
                    pl0 = fmaf(acc[mt][nt][0], al[nt*2],   pl0);
                    pl0 = fmaf(acc[mt][nt][1], al[nt*2+1], pl0);
                    pr0 = fmaf(acc[mt][nt][0], ar[nt*2],   pr0);
                    pr0 = fmaf(acc[mt][nt][1], ar[nt*2+1], pr0);
                    pl1 = fmaf(acc[mt][nt][2], al[nt*2],   pl1);
                    pl1 = fmaf(acc[mt][nt][3], al[nt*2+1], pl1);
                    pr1 = fmaf(acc[mt][nt][2], ar[nt*2],   pr1);
                    pr1 = fmaf(acc[mt][nt][3], ar[nt*2+1], pr1);
                }
#pragma unroll
                for (int off = 1; off <= 2; off <<= 1) {
                    pl0 += __shfl_xor_sync(0xFFFFFFFFu, pl0, off);
                    pr0 += __shfl_xor_sync(0xFFFFFFFFu, pr0, off);
                    pl1 += __shfl_xor_sync(0xFFFFFFFFu, pl1, off);
                    pr1 += __shfl_xor_sync(0xFFFFFFFFu, pr1, off);
                }
                if (tig == 0) {
                    const int rl0 = warp_m * 64 + mt * 16 + gid;
                    const int r0 = block_m + rl0;
                    const int r1 = r0 + 8;
                    if (r0 < M) {
                        g_attn_row[(size_t)r0 * NHEADS + head] =
                            sred[rl0][hl * 2] + pl0;
                        g_attn_col[(size_t)r0 * NHEADS + head] =
                            sred[rl0][hl * 2 + 1] + pr0;
                    }
                    if (r1 < M) {
                        g_attn_row[(size_t)r1 * NHEADS + head] =
                            sred[rl0 + 8][hl * 2] + pl1;
                        g_attn_col[(size_t)r1 * NHEADS + head] =
                            sred[rl0 + 8][hl * 2 + 1] + pr1;
                    }
                }
            }
        }
    }
}

// ---------------------------------------------------------------------------
// Kernel 2: softmax + weighted gather-aggregate.
// ONE WARP per destination (8 dst/CTA). Reads raw row_ptr/col_ind directly
// (uniform int32-vs-int64 layout check; JAX may hand us either).
// ---------------------------------------------------------------------------
__global__ __launch_bounds__(256) void gat_agg_kernel(
    const void* __restrict__ row_ptr_raw,
    const void* __restrict__ col_ind_raw,
    float* __restrict__ out, int n)
{
    const int tid  = threadIdx.x;
    const int wid  = tid >> 5;          // 0..7
    const int lane = tid & 31;
    const int dst  = blockIdx.x * 8 + wid;
    if (dst >= n) return;

    __shared__ int   s_src[8][MAXDEG];
    __shared__ float s_alpha[8][MAXDEG * NHEADS];

    // index layout detection: row_ptr[1]==DEG(16). int32 -> words[1]==16,
    // int64 -> words[1]==0 (high word).
    const bool is64 = (((const int*)row_ptr_raw)[1] == 0);

    int e0, deg;
    if (is64) {
        const long long* rp = (const long long*)row_ptr_raw;
        e0  = (int)rp[dst];
        deg = (int)rp[dst + 1] - e0;
    } else {
        const int* rp = (const int*)row_ptr_raw;
        e0  = rp[dst];
        deg = rp[dst + 1] - e0;
    }
    if (deg > MAXDEG) deg = MAXDEG;

    if (lane < deg) {
        s_src[wid][lane] = is64
            ? (int)((const long long*)col_ind_raw)[e0 + lane]
            : ((const int*)col_ind_raw)[e0 + lane];
    }
    __syncwarp();

    // raw scores + leaky relu: 64 (edge, head) pairs, 2 per lane
#pragma unroll
    for (int p = lane; p < MAXDEG * NHEADS; p += 32) {
        if (p < deg * NHEADS) {
            const int e  = p >> 2;
            const int hh = p & 3;
            float s = g_attn_row[(size_t)dst * NHEADS + hh] +
                      g_attn_col[(size_t)s_src[wid][e] * NHEADS + hh];
            s_alpha[wid][p] = (s >= 0.f) ? s : NEG_SLOPE * s;
        }
    }
    __syncwarp();

    // per-head softmax over deg edges (lanes 0..3)
    if (lane < NHEADS) {
        float m = -1e30f;
        for (int e = 0; e < deg; e++)
            m = fmaxf(m, s_alpha[wid][e * NHEADS + lane]);
        float sum = 0.f;
        for (int e = 0; e < deg; e++) {
            float ex = __expf(s_alpha[wid][e * NHEADS + lane] - m);
            s_alpha[wid][e * NHEADS + lane] = ex;
            sum += ex;
        }
        const float inv = 1.0f / sum;
        for (int e = 0; e < deg; e++)
            s_alpha[wid][e * NHEADS + lane] *= inv;
    }
    __syncwarp();

    // aggregate: lane owns 8 consecutive output floats (all in one head)
    const int h = lane >> 3;            // head = (lane*8)/64
    const int foff = lane * 8;
    float4 acc0 = make_float4(0.f, 0.f, 0.f, 0.f);
    float4 acc1 = make_float4(0.f, 0.f, 0.f, 0.f);

    if (deg == MAXDEG) {
#pragma unroll
        for (int e = 0; e < MAXDEG; e++) {
            const float a = s_alpha[wid][e * NHEADS + h];
            const float* row = g_h + (size_t)s_src[wid][e] * HF + foff;
            const float4 v0 = *reinterpret_cast<const float4*>(row);
            const float4 v1 = *reinterpret_cast<const float4*>(row + 4);
            acc0.x = fmaf(a, v0.x, acc0.x); acc0.y = fmaf(a, v0.y, acc0.y);
            acc0.z = fmaf(a, v0.z, acc0.z); acc0.w = fmaf(a, v0.w, acc0.w);
            acc1.x = fmaf(a, v1.x, acc1.x); acc1.y = fmaf(a, v1.y, acc1.y);
            acc1.z = fmaf(a, v1.z, acc1.z); acc1.w = fmaf(a, v1.w, acc1.w);
        }
    } else {
        for (int e = 0; e < deg; e++) {
            const float a = s_alpha[wid][e * NHEADS + h];
            const float* row = g_h + (size_t)s_src[wid][e] * HF + foff;
            const float4 v0 = *reinterpret_cast<const float4*>(row);
            const float4 v1 = *reinterpret_cast<const float4*>(row + 4);
            acc0.x = fmaf(a, v0.x, acc0.x); acc0.y = fmaf(a, v0.y, acc0.y);
            acc0.z = fmaf(a, v0.z, acc0.z); acc0.w = fmaf(a, v0.w, acc0.w);
            acc1.x = fmaf(a, v1.x, acc1.x); acc1.y = fmaf(a, v1.y, acc1.y);
            acc1.z = fmaf(a, v1.z, acc1.z); acc1.w = fmaf(a, v1.w, acc1.w);
        }
    }
    float* orow = out + (size_t)dst * HF + foff;
    *reinterpret_cast<float4*>(orow)     = acc0;
    *reinterpret_cast<float4*>(orow + 4) = acc1;
}

// ---------------------------------------------------------------------------
// Launch
// Inputs (metadata order): row_ptr(N+1), col_ind(E), col_ptr(N+1), row_ind(E),
// feat(f32,N*256), W(f32,256*256), attn_l(f32,256), attn_r(f32,256)
// Output: f32 [N, 4, 64]
// ---------------------------------------------------------------------------
extern "C" void kernel_launch(void* const* d_in, const int* in_sizes, int n_in,
                              void* d_out, int out_size)
{
    const void*  row_ptr_raw = d_in[0];
    const void*  col_ind_raw = d_in[1];
    const float* feat   = (const float*)d_in[4];
    const float* W      = (const float*)d_in[5];
    const float* attn_l = (const float*)d_in[6];
    const float* attn_r = (const float*)d_in[7];
    float* out = (float*)d_out;

    const int n = in_sizes[0] - 1;        // 50000

    // 1) h = feat @ W (tf32 tensor cores) + fused attn dot products
    dim3 ggrid((n + GBM - 1) / GBM, HF / GBN);
    gemm_tf32_kernel<<<ggrid, 256>>>(feat, W, attn_l, attn_r, n);

    // 2) softmax + aggregate (reads raw indices)
    gat_agg_kernel<<<(n + 7) / 8, 256>>>(row_ptr_raw, col_ind_raw, out, n);
}

// round 11
// speedup vs baseline: 1.0053x; 1.0053x over previous
#include <cuda_runtime.h>
#include <cstdint>

// Problem constants (fixed by the dataset)
#define NMAX      50000
#define IN_FEATS  256
#define NHEADS    4
#define OUTF      64
#define HF        (NHEADS * OUTF)   // 256 = per-node projected width
#define NEG_SLOPE 0.2f
#define MAXDEG    16                // dataset uses fixed deg=16

// ---------------------------------------------------------------------------
// Scratch (no cudaMalloc allowed)
// ---------------------------------------------------------------------------
__device__ float g_h[(size_t)NMAX * HF];        // 51.2 MB projected features
__device__ float g_attn_row[(size_t)NMAX * NHEADS];
__device__ float g_attn_col[(size_t)NMAX * NHEADS];

// ---------------------------------------------------------------------------
// Kernel 1: tf32 tensor-core GEMM  h[M,256] = feat[M,256] @ W[256,256]
// CTA tile 128x128x16, 8 warps in 2(M)x4(N), warp tile 64x32,
// mma.sync.aligned.m16n8k8 tf32, fp32 accumulate. Double-buffered smem.
//
// Fragment-paired smem layouts (all fragment fetches are LDS.64):
//  A: per (mb 0..7, kc 0..1) block of 16 rows x 8 k (128 words):
//     addr = blk*128 + kk*16 + (rr&7)*2 + (rr>>3)
//     -> pair (row gid, row gid+8) at fixed k is contiguous.
//  B: per (kc 0..1, nb 0..15) block of 8 k x 8 cols (64 words), XOR-swizzled:
//     addr = blk*64 + (cc ^ (nb&7))*8 + (kkl&3)*2 + (kkl>>2)
//     -> pair (k tig, k tig+4) at fixed col is contiguous.
//
// Fused epilogue: per-row attn_l/attn_r dot products; even warp_n stages
// partials in smem, odd warp_n combines + plain STG (no atomics, no zeroing).
// ---------------------------------------------------------------------------
#define GBM 128
#define GBN 128
#define GBK 16

__device__ __forceinline__ uint32_t f2tf32(float x) {
    uint32_t r;
    asm("cvt.rna.tf32.f32 %0, %1;" : "=r"(r) : "f"(x));
    return r;
}

__device__ __forceinline__ void mma_tf32(float* c, const uint32_t* a,
                                         const uint32_t* b) {
    asm volatile(
        "mma.sync.aligned.m16n8k8.row.col.f32.tf32.tf32.f32 "
        "{%0,%1,%2,%3}, {%4,%5,%6,%7}, {%8,%9}, {%0,%1,%2,%3};"
        : "+f"(c[0]), "+f"(c[1]), "+f"(c[2]), "+f"(c[3])
        : "r"(a[0]), "r"(a[1]), "r"(a[2]), "r"(a[3]), "r"(b[0]), "r"(b[1]));
}

__global__ __launch_bounds__(256, 2) void gemm_tf32_kernel(
    const float* __restrict__ A,        // [M, 256]
    const float* __restrict__ B,        // [256, 256]
    const float* __restrict__ attn_l,   // [256]
    const float* __restrict__ attn_r,   // [256]
    int M)
{
    const int K = IN_FEATS;
    const int N = HF;

    __shared__ uint32_t As[2][2048];    // 2 x 8 KB
    __shared__ uint32_t Bs[2][2048];    // 2 x 8 KB
    __shared__ float    sred[GBM][4];   // 2 KB: [row][head_local*2 + {l,r}]

    const int tid  = threadIdx.x;
    const int lane = tid & 31;
    const int warp = tid >> 5;
    const int warp_m = warp >> 2;      // 0..1 -> 64-row strip
    const int warp_n = warp & 3;       // 0..3 -> 32-col strip

    const int block_m = blockIdx.x * GBM;
    const int block_n = blockIdx.y * GBN;

    // --- global->smem loader maps ---
    // A: thread covers row a_row, one k-chunk of 8
    const int a_row = tid >> 1;                       // 0..127
    const int a_kc  = tid & 1;                        // 0..1
    const int a_base = ((a_row >> 4) * 2 + a_kc) * 128
                     + (a_row & 7) * 2 + ((a_row >> 3) & 1);
    // B: thread covers k-row b_kk, one 8-col block b_nb
    const int b_kk  = tid >> 4;                       // 0..15
    const int b_nb  = tid & 15;                       // 0..15
    const int b_sw  = b_nb & 7;
    const int b_base = ((b_kk >> 3) * 16 + b_nb) * 64
                     + (b_kk & 3) * 2 + ((b_kk >> 2) & 1);

    const int gid = lane >> 2;                  // 0..7
    const int tig = lane & 3;                   // 0..3

    float acc[4][4][4];
#pragma unroll
    for (int mt = 0; mt < 4; mt++)
#pragma unroll
        for (int nt = 0; nt < 4; nt++)
#pragma unroll
            for (int i = 0; i < 4; i++) acc[mt][nt][i] = 0.0f;

    const int gm = block_m + a_row;
    float4 pa0, pa1, pb0, pb1;

    // ---- load tile 0 into registers, then smem ----
    {
        if (gm < M) {
            const float* ap = A + (size_t)gm * K + a_kc * 8;
            pa0 = *reinterpret_cast<const float4*>(ap);
            pa1 = *reinterpret_cast<const float4*>(ap + 4);
        } else {
            pa0 = make_float4(0.f, 0.f, 0.f, 0.f); pa1 = pa0;
        }
        const float* bp = B + (size_t)b_kk * N + block_n + b_nb * 8;
        pb0 = *reinterpret_cast<const float4*>(bp);
        pb1 = *reinterpret_cast<const float4*>(bp + 4);
    }
    {
        uint32_t* as = &As[0][a_base];
        as[0]  = f2tf32(pa0.x); as[16] = f2tf32(pa0.y);
        as[32] = f2tf32(pa0.z); as[48] = f2tf32(pa0.w);
        as[64] = f2tf32(pa1.x); as[80] = f2tf32(pa1.y);
        as[96] = f2tf32(pa1.z); as[112] = f2tf32(pa1.w);
        uint32_t* bs = &Bs[0][b_base];
        bs[(0 ^ b_sw) << 3] = f2tf32(pb0.x);
        bs[(1 ^ b_sw) << 3] = f2tf32(pb0.y);
        bs[(2 ^ b_sw) << 3] = f2tf32(pb0.z);
        bs[(3 ^ b_sw) << 3] = f2tf32(pb0.w);
        bs[(4 ^ b_sw) << 3] = f2tf32(pb1.x);
        bs[(5 ^ b_sw) << 3] = f2tf32(pb1.y);
        bs[(6 ^ b_sw) << 3] = f2tf32(pb1.z);
        bs[(7 ^ b_sw) << 3] = f2tf32(pb1.w);
    }
    __syncthreads();

    const int NT = K / GBK;   // 16 iterations
    for (int t = 0; t < NT; t++) {
        const int cur = t & 1;

        // prefetch next tile from global
        if (t < NT - 1) {
            const int k0 = (t + 1) * GBK;
            if (gm < M) {
                const float* ap = A + (size_t)gm * K + k0 + a_kc * 8;
                pa0 = *reinterpret_cast<const float4*>(ap);
                pa1 = *reinterpret_cast<const float4*>(ap + 4);
            } else {
                pa0 = make_float4(0.f, 0.f, 0.f, 0.f); pa1 = pa0;
            }
            const float* bp = B + (size_t)(k0 + b_kk) * N + block_n + b_nb * 8;
            pb0 = *reinterpret_cast<const float4*>(bp);
            pb1 = *reinterpret_cast<const float4*>(bp + 4);
        }

        // compute: 2 k-chunks of 8
#pragma unroll
        for (int kc = 0; kc < 2; kc++) {
            uint32_t af[4][4], bf[4][2];
#pragma unroll
            for (int mt = 0; mt < 4; mt++) {
                const int baseA = (((warp_m * 4 + mt) * 2 + kc) << 7)
                                + gid * 2;
                const uint2 a01 = *reinterpret_cast<const uint2*>(
                    &As[cur][baseA + tig * 16]);
                const uint2 a23 = *reinterpret_cast<const uint2*>(
                    &As[cur][baseA + (tig + 4) * 16]);
                af[mt][0] = a01.x; af[mt][1] = a01.y;
                af[mt][2] = a23.x; af[mt][3] = a23.y;
            }
#pragma unroll
            for (int nt = 0; nt < 4; nt++) {
                const int nb = warp_n * 4 + nt;
                const uint2 b01 = *reinterpret_cast<const uint2*>(
                    &Bs[cur][((kc * 16 + nb) << 6)
                             + ((gid ^ (nb & 7)) << 3) + tig * 2]);
                bf[nt][0] = b01.x; bf[nt][1] = b01.y;
            }
#pragma unroll
            for (int mt = 0; mt < 4; mt++)
#pragma unroll
                for (int nt = 0; nt < 4; nt++)
                    mma_tf32(acc[mt][nt], af[mt], bf[nt]);
        }

        // store prefetched tile to other buffer
        if (t < NT - 1) {
            const int nxt = (t + 1) & 1;
            uint32_t* as = &As[nxt][a_base];
            as[0]  = f2tf32(pa0.x); as[16] = f2tf32(pa0.y);
            as[32] = f2tf32(pa0.z); as[48] = f2tf32(pa0.w);
            as[64] = f2tf32(pa1.x); as[80] = f2tf32(pa1.y);
            as[96] = f2tf32(pa1.z); as[112] = f2tf32(pa1.w);
            uint32_t* bs = &Bs[nxt][b_base];
            bs[(0 ^ b_sw) << 3] = f2tf32(pb0.x);
            bs[(1 ^ b_sw) << 3] = f2tf32(pb0.y);
            bs[(2 ^ b_sw) << 3] = f2tf32(pb0.z);
            bs[(3 ^ b_sw) << 3] = f2tf32(pb0.w);
            bs[(4 ^ b_sw) << 3] = f2tf32(pb1.x);
            bs[(5 ^ b_sw) << 3] = f2tf32(pb1.y);
            bs[(6 ^ b_sw) << 3] = f2tf32(pb1.z);
            bs[(7 ^ b_sw) << 3] = f2tf32(pb1.w);
            __syncthreads();
        }
    }

    // ---- epilogue 1: write h ----
#pragma unroll
    for (int mt = 0; mt < 4; mt++) {
        const int r0 = block_m + warp_m * 64 + mt * 16 + gid;
        const int r1 = r0 + 8;
#pragma unroll
        for (int nt = 0; nt < 4; nt++) {
            const int cn = block_n + warp_n * 32 + nt * 8 + tig * 2;
            if (r0 < M) {
                float2 v = make_float2(acc[mt][nt][0], acc[mt][nt][1]);
                *reinterpret_cast<float2*>(g_h + (size_t)r0 * HF + cn) = v;
            }
            if (r1 < M) {
                float2 v = make_float2(acc[mt][nt][2], acc[mt][nt][3]);
                *reinterpret_cast<float2*>(g_h + (size_t)r1 * HF + cn) = v;
            }
        }
    }

    // ---- epilogue 2: fused attn dot products (smem reduce across warp_n
    //      pairs, then plain store; each (row, head) owned by this CTA) ----
    {
        const int hl   = warp_n >> 1;           // head-local: 0..1
        const int head = (block_n >> 6) + hl;   // global head
        float al[8], ar[8];
#pragma unroll
        for (int nt = 0; nt < 4; nt++) {
            const int c = block_n + warp_n * 32 + nt * 8 + tig * 2;
            al[nt * 2]     = attn_l[c];
            al[nt * 2 + 1] = attn_l[c + 1];
            ar[nt * 2]     = attn_r[c];
            ar[nt * 2 + 1] = attn_r[c + 1];
        }

        __syncthreads();   // smem buffers free; sred becomes valid

        // phase 1: even warp_n stages partials
        if ((warp_n & 1) == 0) {
#pragma unroll
            for (int mt = 0; mt < 4; mt++) {
                float pl0 = 0.f, pr0 = 0.f, pl1 = 0.f, pr1 = 0.f;
#pragma unroll
                for (int nt = 0; nt < 4; nt++) {
                    pl0 = fmaf(acc[mt][nt][0], al[nt*2],   pl0);
                    pl0 = fmaf(acc[mt][nt][1], al[nt*2+1], pl0);
                    pr0 = fmaf(acc[mt][nt][0], ar[nt*2],   pr0);
                    pr0 = fmaf(acc[mt][nt][1], ar[nt*2+1], pr0);
                    pl1 = fmaf(acc[mt][nt][2], al[nt*2],   pl1);
                    pl1 = fmaf(acc[mt][nt][3], al[nt*2+1], pl1);
                    pr1 = fmaf(acc[mt][nt][2], ar[nt*2],   pr1);
                    pr1 = fmaf(acc[mt][nt][3], ar[nt*2+1], pr1);
                }
#pragma unroll
                for (int off = 1; off <= 2; off <<= 1) {
                    pl0 += __shfl_xor_sync(0xFFFFFFFFu, pl0, off);
                    pr0 += __shfl_xor_sync(0xFFFFFFFFu, pr0, off);
                    pl1 += __shfl_xor_sync(0xFFFFFFFFu, pl1, off);
                    pr1 += __shfl_xor_sync(0xFFFFFFFFu, pr1, off);
                }
                if (tig == 0) {
                    const int rl0 = warp_m * 64 + mt * 16 + gid;
                    sred[rl0][hl * 2]     = pl0;
                    sred[rl0][hl * 2 + 1] = pr0;
                    sred[rl0 + 8][hl * 2]     = pl1;
                    sred[rl0 + 8][hl * 2 + 1] = pr1;
                }
            }
        }
        __syncthreads();

        // phase 2: odd warp_n combines and stores
        if ((warp_n & 1) == 1) {
#pragma unroll
            for (int mt = 0; mt < 4; mt++) {
                float pl0 = 0.f, pr0 = 0.f, pl1 = 0.f, pr1 = 0.f;
#pragma unroll
                for (int nt = 0; nt < 4; nt++) {
                    pl0 = fmaf(acc[mt][nt][0], al[nt*2],   pl0);
                    pl0 = fmaf(acc[mt][nt][1], al[nt*2+1], pl0);
                    pr0 = fmaf(acc[mt][nt][0], ar[nt*2],   pr0);
                    pr0 = fmaf(acc[mt][nt][1], ar[nt*2+1], pr0);
                    pl1 = fmaf(acc[mt][nt][2], al[nt*2],   pl1);
                    pl1 = fmaf(acc[mt][nt][3], al[nt*2+1], pl1);
                    pr1 = fmaf(acc[mt][nt][2], ar[nt*2],   pr1);
                    pr1 = fmaf(acc[mt][nt][3], ar[nt*2+1], pr1);
                }
#pragma unroll
                for (int off = 1; off <= 2; off <<= 1) {
                    pl0 += __shfl_xor_sync(0xFFFFFFFFu, pl0, off);
                    pr0 += __shfl_xor_sync(0xFFFFFFFFu, pr0, off);
                    pl1 += __shfl_xor_sync(0xFFFFFFFFu, pl1, off);
                    pr1 += __shfl_xor_sync(0xFFFFFFFFu, pr1, off);
                }
                if (tig == 0) {
                    const int rl0 = warp_m * 64 + mt * 16 + gid;
                    const int r0 = block_m + rl0;
                    const int r1 = r0 + 8;
                    if (r0 < M) {
                        g_attn_row[(size_t)r0 * NHEADS + head] =
                            sred[rl0][hl * 2] + pl0;
                        g_attn_col[(size_t)r0 * NHEADS + head] =
                            sred[rl0][hl * 2 + 1] + pr0;
                    }
                    if (r1 < M) {
                        g_attn_row[(size_t)r1 * NHEADS + head] =
                            sred[rl0 + 8][hl * 2] + pl1;
                        g_attn_col[(size_t)r1 * NHEADS + head] =
                            sred[rl0 + 8][hl * 2 + 1] + pr1;
                    }
                }
            }
        }
    }
}

// ---------------------------------------------------------------------------
// Kernel 2: softmax + weighted gather-aggregate.
// ONE WARP per destination (8 dst/CTA). Reads raw row_ptr/col_ind directly
// (uniform int32-vs-int64 layout check; JAX may hand us either).
// ---------------------------------------------------------------------------
__global__ __launch_bounds__(256) void gat_agg_kernel(
    const void* __restrict__ row_ptr_raw,
    const void* __restrict__ col_ind_raw,
    float* __restrict__ out, int n)
{
    const int tid  = threadIdx.x;
    const int wid  = tid >> 5;          // 0..7
    const int lane = tid & 31;
    const int dst  = blockIdx.x * 8 + wid;
    if (dst >= n) return;

    __shared__ int   s_src[8][MAXDEG];
    __shared__ float s_alpha[8][MAXDEG * NHEADS];

    // index layout detection: row_ptr[1]==DEG(16). int32 -> words[1]==16,
    // int64 -> words[1]==0 (high word).
    const bool is64 = (((const int*)row_ptr_raw)[1] == 0);

    int e0, deg;
    if (is64) {
        const long long* rp = (const long long*)row_ptr_raw;
        e0  = (int)rp[dst];
        deg = (int)rp[dst + 1] - e0;
    } else {
        const int* rp = (const int*)row_ptr_raw;
        e0  = rp[dst];
        deg = rp[dst + 1] - e0;
    }
    if (deg > MAXDEG) deg = MAXDEG;

    if (lane < deg) {
        s_src[wid][lane] = is64
            ? (int)((const long long*)col_ind_raw)[e0 + lane]
            : ((const int*)col_ind_raw)[e0 + lane];
    }
    __syncwarp();

    // raw scores + leaky relu: 64 (edge, head) pairs, 2 per lane
#pragma unroll
    for (int p = lane; p < MAXDEG * NHEADS; p += 32) {
        if (p < deg * NHEADS) {
            const int e  = p >> 2;
            const int hh = p & 3;
            float s = g_attn_row[(size_t)dst * NHEADS + hh] +
                      g_attn_col[(size_t)s_src[wid][e] * NHEADS + hh];
            s_alpha[wid][p] = (s >= 0.f) ? s : NEG_SLOPE * s;
        }
    }
    __syncwarp();

    // per-head softmax over deg edges (lanes 0..3)
    if (lane < NHEADS) {
        float m = -1e30f;
        for (int e = 0; e < deg; e++)
            m = fmaxf(m, s_alpha[wid][e * NHEADS + lane]);
        float sum = 0.f;
        for (int e = 0; e < deg; e++) {
            float ex = __expf(s_alpha[wid][e * NHEADS + lane] - m);
            s_alpha[wid][e * NHEADS + lane] = ex;
            sum += ex;
        }
        const float inv = 1.0f / sum;
        for (int e = 0; e < deg; e++)
            s_alpha[wid][e * NHEADS + lane] *= inv;
    }
    __syncwarp();

    // aggregate: lane owns 8 consecutive output floats (all in one head)
    const int h = lane >> 3;            // head = (lane*8)/64
    const int foff = lane * 8;
    float4 acc0 = make_float4(0.f, 0.f, 0.f, 0.f);
    float4 acc1 = make_float4(0.f, 0.f, 0.f, 0.f);

    if (deg == MAXDEG) {
#pragma unroll
        for (int e = 0; e < MAXDEG; e++) {
            const float a = s_alpha[wid][e * NHEADS + h];
            const float* row = g_h + (size_t)s_src[wid][e] * HF + foff;
            const float4 v0 = *reinterpret_cast<const float4*>(row);
            const float4 v1 = *reinterpret_cast<const float4*>(row + 4);
            acc0.x = fmaf(a, v0.x, acc0.x); acc0.y = fmaf(a, v0.y, acc0.y);
            acc0.z = fmaf(a, v0.z, acc0.z); acc0.w = fmaf(a, v0.w, acc0.w);
            acc1.x = fmaf(a, v1.x, acc1.x); acc1.y = fmaf(a, v1.y, acc1.y);
            acc1.z = fmaf(a, v1.z, acc1.z); acc1.w = fmaf(a, v1.w, acc1.w);
        }
    } else {
        for (int e = 0; e < deg; e++) {
            const float a = s_alpha[wid][e * NHEADS + h];
            const float* row = g_h + (size_t)s_src[wid][e] * HF + foff;
            const float4 v0 = *reinterpret_cast<const float4*>(row);
            const float4 v1 = *reinterpret_cast<const float4*>(row + 4);
            acc0.x = fmaf(a, v0.x, acc0.x); acc0.y = fmaf(a, v0.y, acc0.y);
            acc0.z = fmaf(a, v0.z, acc0.z); acc0.w = fmaf(a, v0.w, acc0.w);
            acc1.x = fmaf(a, v1.x, acc1.x); acc1.y = fmaf(a, v1.y, acc1.y);
            acc1.z = fmaf(a, v1.z, acc1.z); acc1.w = fmaf(a, v1.w, acc1.w);
        }
    }
    float* orow = out + (size_t)dst * HF + foff;
    *reinterpret_cast<float4*>(orow)     = acc0;
    *reinterpret_cast<float4*>(orow + 4) = acc1;
}

// ---------------------------------------------------------------------------
// Launch
// Inputs (metadata order): row_ptr(N+1), col_ind(E), col_ptr(N+1), row_ind(E),
// feat(f32,N*256), W(f32,256*256), attn_l(f32,256), attn_r(f32,256)
// Output: f32 [N, 4, 64]
// ---------------------------------------------------------------------------
extern "C" void kernel_launch(void* const* d_in, const int* in_sizes, int n_in,
                              void* d_out, int out_size)
{
    const void*  row_ptr_raw = d_in[0];
    const void*  col_ind_raw = d_in[1];
    const float* feat   = (const float*)d_in[4];
    const float* W      = (const float*)d_in[5];
    const float* attn_l = (const float*)d_in[6];
    const float* attn_r = (const float*)d_in[7];
    float* out = (float*)d_out;

    const int n = in_sizes[0] - 1;        // 50000

    // 1) h = feat @ W (tf32 tensor cores) + fused attn dot products
    dim3 ggrid((n + GBM - 1) / GBM, HF / GBN);
    gemm_tf32_kernel<<<ggrid, 256>>>(feat, W, attn_l, attn_r, n);

    // 2) softmax + aggregate (reads raw indices)
    gat_agg_kernel<<<(n + 7) / 8, 256>>>(row_ptr_raw, col_ind_raw, out, n);
}

// round 12
// speedup vs baseline: 1.1111x; 1.1052x over previous
#include <cuda_runtime.h>
#include <cstdint>

// Problem constants (fixed by the dataset)
#define NMAX      50000
#define IN_FEATS  256
#define NHEADS    4
#define OUTF      64
#define HF        (NHEADS * OUTF)   // 256 = per-node projected width
#define NEG_SLOPE 0.2f
#define MAXDEG    16                // dataset uses fixed deg=16

// ---------------------------------------------------------------------------
// Scratch (no cudaMalloc allowed)
// ---------------------------------------------------------------------------
__device__ float g_h[(size_t)NMAX * HF];            // 51.2 MB projected feats
__device__ float g_attn_row[(size_t)NMAX * NHEADS];
__device__ float g_attn_col[(size_t)NMAX * NHEADS];
__device__ float g_feat_cvt[(size_t)NMAX * IN_FEATS]; // tf32-rounded feat
__device__ float g_W_cvt[IN_FEATS * HF];              // tf32-rounded W

__device__ __forceinline__ float tf32r(float x) {
    uint32_t r;
    asm("cvt.rna.tf32.f32 %0, %1;" : "=r"(r) : "f"(x));
    return __uint_as_float(r);
}

// ---------------------------------------------------------------------------
// Kernel 0: round feat and W to tf32 (rna) once, so the GEMM can stream them
// through cp.async with no per-fragment conversion (keeps rel_err at rna).
// ---------------------------------------------------------------------------
__global__ void cvt_tf32_kernel(const float4* __restrict__ feat,
                                const float4* __restrict__ W, int nfeat4)
{
    const int i = blockIdx.x * blockDim.x + threadIdx.x;
    if (i < nfeat4) {
        float4 v = feat[i];
        v.x = tf32r(v.x); v.y = tf32r(v.y); v.z = tf32r(v.z); v.w = tf32r(v.w);
        reinterpret_cast<float4*>(g_feat_cvt)[i] = v;
    }
    if (i < (IN_FEATS * HF) / 4) {
        float4 v = W[i];
        v.x = tf32r(v.x); v.y = tf32r(v.y); v.z = tf32r(v.z); v.w = tf32r(v.w);
        reinterpret_cast<float4*>(g_W_cvt)[i] = v;
    }
}

// ---------------------------------------------------------------------------
// Kernel 1: tf32 tensor-core GEMM  h[M,256] = feat[M,256] @ W[256,256]
// CTA tile 128x128x16, 8 warps 2(M)x4(N), warp tile 64x32,
// mma.sync m16n8k8 tf32 / fp32 accum.
// 3-stage cp.async ring in dynamic smem (A stride 20, B stride 136 —
// both conflict-free for the fragment LDS patterns, both 16B-chunk aligned).
// Fused epilogue: attn_l/attn_r row dots via smem cross-warp reduce + STG.
// ---------------------------------------------------------------------------
#define GBM 128
#define GBN 128
#define GBK 16
#define NSTAGE 3
#define A_ST 20                       // floats per A row
#define B_ST 136                      // floats per B k-row
#define STAGE_FLOATS (GBM * A_ST + GBK * B_ST)   // 2560 + 2176 = 4736
#define SRED_OFF (NSTAGE * STAGE_FLOATS)
#define GEMM_SMEM_BYTES ((SRED_OFF + GBM * 4) * 4)   // 58880

__device__ __forceinline__ void cp16(float* dst, const float* src, int sz) {
    unsigned d = (unsigned)__cvta_generic_to_shared(dst);
    asm volatile("cp.async.cg.shared.global [%0], [%1], 16, %2;"
                 :: "r"(d), "l"(src), "r"(sz) : "memory");
}
__device__ __forceinline__ void cp_commit() {
    asm volatile("cp.async.commit_group;" ::: "memory");
}

__device__ __forceinline__ void mma_tf32(float* c, const uint32_t* a,
                                         const uint32_t* b) {
    asm volatile(
        "mma.sync.aligned.m16n8k8.row.col.f32.tf32.tf32.f32 "
        "{%0,%1,%2,%3}, {%4,%5,%6,%7}, {%8,%9}, {%0,%1,%2,%3};"
        : "+f"(c[0]), "+f"(c[1]), "+f"(c[2]), "+f"(c[3])
        : "r"(a[0]), "r"(a[1]), "r"(a[2]), "r"(a[3]), "r"(b[0]), "r"(b[1]));
}

__global__ __launch_bounds__(256, 2) void gemm_tf32_kernel(
    const float* __restrict__ attn_l,   // [256]
    const float* __restrict__ attn_r,   // [256]
    int M)
{
    extern __shared__ float dynsm[];
    const float* A = g_feat_cvt;
    const float* B = g_W_cvt;
    const int K = IN_FEATS;
    const int N = HF;

    const int tid  = threadIdx.x;
    const int lane = tid & 31;
    const int warp = tid >> 5;
    const int warp_m = warp >> 2;      // 0..1
    const int warp_n = warp & 3;       // 0..3
    const int gid = lane >> 2;         // 0..7
    const int tig = lane & 3;          // 0..3

    const int block_m = blockIdx.x * GBM;
    const int block_n = blockIdx.y * GBN;

    // loader maps
    const int a_row = tid >> 1;                 // 0..127
    const int a_off = (tid & 1) * 8;            // float offset 0 or 8
    const int gm    = block_m + a_row;
    const int a_sz  = (gm < M) ? 16 : 0;
    const int b_kk  = tid >> 4;                 // 0..15
    const int b_off = (tid & 15) * 8;           // float col offset

    float acc[4][4][4];
#pragma unroll
    for (int mt = 0; mt < 4; mt++)
#pragma unroll
        for (int nt = 0; nt < 4; nt++)
#pragma unroll
            for (int i = 0; i < 4; i++) acc[mt][nt][i] = 0.0f;

    const int NT = K / GBK;   // 16

    // ---- prologue: issue tiles 0 and 1 ----
#pragma unroll
    for (int s = 0; s < NSTAGE - 1; s++) {
        float* st = dynsm + s * STAGE_FLOATS;
        const int k0 = s * GBK;
        {
            float* d = st + a_row * A_ST + a_off;
            const float* g = A + (size_t)gm * K + k0 + a_off;
            cp16(d, g, a_sz); cp16(d + 4, g + 4, a_sz);
        }
        {
            float* d = st + GBM * A_ST + b_kk * B_ST + b_off;
            const float* g = B + (size_t)(k0 + b_kk) * N + block_n + b_off;
            cp16(d, g, 16); cp16(d + 4, g + 4, 16);
        }
        cp_commit();
    }

    for (int t = 0; t < NT; t++) {
        // issue tile t+2
        if (t + NSTAGE - 1 < NT) {
            float* st = dynsm + ((t + NSTAGE - 1) % NSTAGE) * STAGE_FLOATS;
            const int k0 = (t + NSTAGE - 1) * GBK;
            {
                float* d = st + a_row * A_ST + a_off;
                const float* g = A + (size_t)gm * K + k0 + a_off;
                cp16(d, g, a_sz); cp16(d + 4, g + 4, a_sz);
            }
            {
                float* d = st + GBM * A_ST + b_kk * B_ST + b_off;
                const float* g = B + (size_t)(k0 + b_kk) * N + block_n + b_off;
                cp16(d, g, 16); cp16(d + 4, g + 4, 16);
            }
        }
        cp_commit();   // always, to keep group counts aligned

        asm volatile("cp.async.wait_group 2;" ::: "memory");
        __syncthreads();

        const float* As = dynsm + (t % NSTAGE) * STAGE_FLOATS;
        const float* Bs = As + GBM * A_ST;

#pragma unroll
        for (int kc = 0; kc < 2; kc++) {
            const int kb = kc * 8;
            uint32_t af[4][4], bf[4][2];
#pragma unroll
            for (int mt = 0; mt < 4; mt++) {
                const int r0 = warp_m * 64 + mt * 16 + gid;
                af[mt][0] = __float_as_uint(As[r0 * A_ST + kb + tig]);
                af[mt][1] = __float_as_uint(As[(r0 + 8) * A_ST + kb + tig]);
                af[mt][2] = __float_as_uint(As[r0 * A_ST + kb + tig + 4]);
                af[mt][3] = __float_as_uint(As[(r0 + 8) * A_ST + kb + tig + 4]);
            }
#pragma unroll
            for (int nt = 0; nt < 4; nt++) {
                const int cn = warp_n * 32 + nt * 8 + gid;
                bf[nt][0] = __float_as_uint(Bs[(kb + tig) * B_ST + cn]);
                bf[nt][1] = __float_as_uint(Bs[(kb + tig + 4) * B_ST + cn]);
            }
#pragma unroll
            for (int mt = 0; mt < 4; mt++)
#pragma unroll
                for (int nt = 0; nt < 4; nt++)
                    mma_tf32(acc[mt][nt], af[mt], bf[nt]);
        }
        __syncthreads();   // protect slot (t%NSTAGE) before it is re-filled
    }

    // ---- epilogue 1: write h ----
#pragma unroll
    for (int mt = 0; mt < 4; mt++) {
        const int r0 = block_m + warp_m * 64 + mt * 16 + gid;
        const int r1 = r0 + 8;
#pragma unroll
        for (int nt = 0; nt < 4; nt++) {
            const int cn = block_n + warp_n * 32 + nt * 8 + tig * 2;
            if (r0 < M) {
                float2 v = make_float2(acc[mt][nt][0], acc[mt][nt][1]);
                *reinterpret_cast<float2*>(g_h + (size_t)r0 * HF + cn) = v;
            }
            if (r1 < M) {
                float2 v = make_float2(acc[mt][nt][2], acc[mt][nt][3]);
                *reinterpret_cast<float2*>(g_h + (size_t)r1 * HF + cn) = v;
            }
        }
    }

    // ---- epilogue 2: fused attn dot products (smem cross-warp reduce) ----
    {
        float* sred = dynsm + SRED_OFF;         // [128][4]
        const int hl   = warp_n >> 1;           // head-local 0..1
        const int head = (block_n >> 6) + hl;   // global head
        float al[8], ar[8];
#pragma unroll
        for (int nt = 0; nt < 4; nt++) {
            const int c = block_n + warp_n * 32 + nt * 8 + tig * 2;
            al[nt * 2]     = attn_l[c];
            al[nt * 2 + 1] = attn_l[c + 1];
            ar[nt * 2]     = attn_r[c];
            ar[nt * 2 + 1] = attn_r[c + 1];
        }

        __syncthreads();

        if ((warp_n & 1) == 0) {
#pragma unroll
            for (int mt = 0; mt < 4; mt++) {
                float pl0 = 0.f, pr0 = 0.f, pl1 = 0.f, pr1 = 0.f;
#pragma unroll
                for (int nt = 0; nt < 4; nt++) {
                    pl0 = fmaf(acc[mt][nt][0], al[nt*2],   pl0);
                    pl0 = fmaf(acc[mt][nt][1], al[nt*2+1], pl0);
                    pr0 = fmaf(acc[mt][nt][0], ar[nt*2],   pr0);
                    pr0 = fmaf(acc[mt][nt][1], ar[nt*2+1], pr0);
                    pl1 = fmaf(acc[mt][nt][2], al[nt*2],   pl1);
                    pl1 = fmaf(acc[mt][nt][3], al[nt*2+1], pl1);
                    pr1 = fmaf(acc[mt][nt][2], ar[nt*2],   pr1);
                    pr1 = fmaf(acc[mt][nt][3], ar[nt*2+1], pr1);
                }
#pragma unroll
                for (int off = 1; off <= 2; off <<= 1) {
                    pl0 += __shfl_xor_sync(0xFFFFFFFFu, pl0, off);
                    pr0 += __shfl_xor_sync(0xFFFFFFFFu, pr0, off);
                    pl1 += __shfl_xor_sync(0xFFFFFFFFu, pl1, off);
                    pr1 += __shfl_xor_sync(0xFFFFFFFFu, pr1, off);
                }
                if (tig == 0) {
                    const int rl0 = warp_m * 64 + mt * 16 + gid;
                    sred[rl0 * 4 + hl * 2]           = pl0;
                    sred[rl0 * 4 + hl * 2 + 1]       = pr0;
                    sred[(rl0 + 8) * 4 + hl * 2]     = pl1;
                    sred[(rl0 + 8) * 4 + hl * 2 + 1] = pr1;
                }
            }
        }
        __syncthreads();

        if ((warp_n & 1) == 1) {
#pragma unroll
            for (int mt = 0; mt < 4; mt++) {
                float pl0 = 0.f, pr0 = 0.f, pl1 = 0.f, pr1 = 0.f;
#pragma unroll
                for (int nt = 0; nt < 4; nt++) {
                    pl0 = fmaf(acc[mt][nt][0], al[nt*2],   pl0);
                    pl0 = fmaf(acc[mt][nt][1], al[nt*2+1], pl0);
                    pr0 = fmaf(acc[mt][nt][0], ar[nt*2],   pr0);
                    pr0 = fmaf(acc[mt][nt][1], ar[nt*2+1], pr0);
                    pl1 = fmaf(acc[mt][nt][2], al[nt*2],   pl1);
                    pl1 = fmaf(acc[mt][nt][3], al[nt*2+1], pl1);
                    pr1 = fmaf(acc[mt][nt][2], ar[nt*2],   pr1);
                    pr1 = fmaf(acc[mt][nt][3], ar[nt*2+1], pr1);
                }
#pragma unroll
                for (int off = 1; off <= 2; off <<= 1) {
                    pl0 += __shfl_xor_sync(0xFFFFFFFFu, pl0, off);
                    pr0 += __shfl_xor_sync(0xFFFFFFFFu, pr0, off);
                    pl1 += __shfl_xor_sync(0xFFFFFFFFu, pl1, off);
                    pr1 += __shfl_xor_sync(0xFFFFFFFFu, pr1, off);
                }
                if (tig == 0) {
                    const int rl0 = warp_m * 64 + mt * 16 + gid;
                    const int r0 = block_m + rl0;
                    const int r1 = r0 + 8;
                    if (r0 < M) {
                        g_attn_row[(size_t)r0 * NHEADS + head] =
                            sred[rl0 * 4 + hl * 2] + pl0;
                        g_attn_col[(size_t)r0 * NHEADS + head] =
                            sred[rl0 * 4 + hl * 2 + 1] + pr0;
                    }
                    if (r1 < M) {
                        g_attn_row[(size_t)r1 * NHEADS + head] =
                            sred[(rl0 + 8) * 4 + hl * 2] + pl1;
                        g_attn_col[(size_t)r1 * NHEADS + head] =
                            sred[(rl0 + 8) * 4 + hl * 2 + 1] + pr1;
                    }
                }
            }
        }
    }
}

// ---------------------------------------------------------------------------
// Kernel 2: softmax + weighted gather-aggregate.
// PROVEN-BEST shape: 4 destinations per CTA, 64 threads per destination,
// float4 gathers (69.6us measured). Reads raw row_ptr/col_ind (int32/int64).
// ---------------------------------------------------------------------------
__global__ __launch_bounds__(256) void gat_agg_kernel(
    const void* __restrict__ row_ptr_raw,
    const void* __restrict__ col_ind_raw,
    float* __restrict__ out, int n)
{
    const int tid = threadIdx.x;
    const int group = tid >> 6;         // 0..3
    const int gt = tid & 63;            // thread within group
    const int dst = blockIdx.x * 4 + group;
    const bool valid = dst < n;

    __shared__ int   s_src[4][MAXDEG];
    __shared__ float s_alpha[4][MAXDEG * NHEADS];

    const bool is64 = (((const int*)row_ptr_raw)[1] == 0);

    int e0 = 0, deg = 0;
    if (valid) {
        if (is64) {
            const long long* rp = (const long long*)row_ptr_raw;
            e0  = (int)rp[dst];
            deg = (int)rp[dst + 1] - e0;
        } else {
            const int* rp = (const int*)row_ptr_raw;
            e0  = rp[dst];
            deg = rp[dst + 1] - e0;
        }
        if (deg > MAXDEG) deg = MAXDEG;
    }
    if (valid && gt < deg) {
        s_src[group][gt] = is64
            ? (int)((const long long*)col_ind_raw)[e0 + gt]
            : ((const int*)col_ind_raw)[e0 + gt];
    }
    __syncthreads();

    // raw scores + leaky relu: one thread per (edge, head)
    if (valid && gt < deg * NHEADS) {
        const int e = gt >> 2;
        const int hh = gt & 3;
        float s = g_attn_row[(size_t)dst * NHEADS + hh] +
                  g_attn_col[(size_t)s_src[group][e] * NHEADS + hh];
        s_alpha[group][gt] = (s >= 0.f) ? s : NEG_SLOPE * s;
    }
    __syncthreads();

    // per-head softmax over deg edges
    if (valid && gt < NHEADS) {
        float m = -1e30f;
        for (int e = 0; e < deg; e++)
            m = fmaxf(m, s_alpha[group][e * NHEADS + gt]);
        float sum = 0.f;
        for (int e = 0; e < deg; e++) {
            float ex = __expf(s_alpha[group][e * NHEADS + gt] - m);
            s_alpha[group][e * NHEADS + gt] = ex;
            sum += ex;
        }
        const float inv = 1.0f / sum;
        for (int e = 0; e < deg; e++)
            s_alpha[group][e * NHEADS + gt] *= inv;
    }
    __syncthreads();
    if (!valid) return;

    // aggregate: thread owns 4 consecutive output floats
    const int h = gt >> 4;
    const int foff = gt * 4;
    float4 acc = make_float4(0.f, 0.f, 0.f, 0.f);

    if (deg == MAXDEG) {
#pragma unroll
        for (int e = 0; e < MAXDEG; e++) {
            const float a = s_alpha[group][e * NHEADS + h];
            const float4 v = *reinterpret_cast<const float4*>(
                g_h + (size_t)s_src[group][e] * HF + foff);
            acc.x = fmaf(a, v.x, acc.x);
            acc.y = fmaf(a, v.y, acc.y);
            acc.z = fmaf(a, v.z, acc.z);
            acc.w = fmaf(a, v.w, acc.w);
        }
    } else {
        for (int e = 0; e < deg; e++) {
            const float a = s_alpha[group][e * NHEADS + h];
            const float4 v = *reinterpret_cast<const float4*>(
                g_h + (size_t)s_src[group][e] * HF + foff);
            acc.x = fmaf(a, v.x, acc.x);
            acc.y = fmaf(a, v.y, acc.y);
            acc.z = fmaf(a, v.z, acc.z);
            acc.w = fmaf(a, v.w, acc.w);
        }
    }
    *reinterpret_cast<float4*>(out + (size_t)dst * HF + foff) = acc;
}

// ---------------------------------------------------------------------------
// Launch
// Inputs (metadata order): row_ptr(N+1), col_ind(E), col_ptr(N+1), row_ind(E),
// feat(f32,N*256), W(f32,256*256), attn_l(f32,256), attn_r(f32,256)
// Output: f32 [N, 4, 64]
// ---------------------------------------------------------------------------
extern "C" void kernel_launch(void* const* d_in, const int* in_sizes, int n_in,
                              void* d_out, int out_size)
{
    const void*  row_ptr_raw = d_in[0];
    const void*  col_ind_raw = d_in[1];
    const float* feat   = (const float*)d_in[4];
    const float* attn_l = (const float*)d_in[6];
    const float* attn_r = (const float*)d_in[7];
    float* out = (float*)d_out;

    const int n = in_sizes[0] - 1;        // 50000

    // 0) tf32-round feat and W into scratch
    {
        const int nfeat4 = (n * IN_FEATS) / 4;
        cvt_tf32_kernel<<<(nfeat4 + 255) / 256, 256>>>(
            (const float4*)feat, (const float4*)d_in[5], nfeat4);
    }

    // 1) h = feat @ W (tf32 tensor cores, cp.async 3-stage) + fused attn dots
    static bool attr_set = false;
    if (!attr_set) {
        cudaFuncSetAttribute(gemm_tf32_kernel,
                             cudaFuncAttributeMaxDynamicSharedMemorySize,
                             GEMM_SMEM_BYTES);
        attr_set = true;
    }
    dim3 ggrid((n + GBM - 1) / GBM, HF / GBN);
    gemm_tf32_kernel<<<ggrid, 256, GEMM_SMEM_BYTES>>>(attn_l, attn_r, n);

    // 2) softmax + aggregate (reads raw indices)
    gat_agg_kernel<<<(n + 3) / 4, 256>>>(row_ptr_raw, col_ind_raw, out, n);
}